// round 2
// baseline (speedup 1.0000x reference)
#include <cuda_runtime.h>

// Problem constants
#define BATCH   8
#define IN_CH   256
#define HSZ     32
#define QB      36      // K blocks
#define PB      8       // output blocks
#define BLK     64
#define KDIM    2304    // QB * BLK
#define NDIM    512     // PB * BLK
#define MDIM    8192    // BATCH * 1024
#define LSPAT   1024

// Scratch (static device allocations are allowed; cudaMalloc is not)
__device__ float g_X[(size_t)MDIM * KDIM];    // 75.5 MB im2col matrix
__device__ float g_WT[(size_t)KDIM * NDIM];   // 4.7 MB expanded circulant weight, K-major

// ---------------------------------------------------------------------------
// Kernel 0: expand block-circulant weight into dense K-major matrix
//   W_T[c][o] = w[p][q][(n - m) & 63],  o = p*64+n, c = q*64+m
// ---------------------------------------------------------------------------
__global__ void wprep_kernel(const float* __restrict__ w) {
    int c = blockIdx.x;          // 0..2303
    int o = threadIdx.x;         // 0..511
    int p = o >> 6, n = o & 63;
    int q = c >> 6, m = c & 63;
    g_WT[c * NDIM + o] = w[(p * QB + q) * BLK + ((n - m) & 63)];
}

// ---------------------------------------------------------------------------
// Kernel 1: im2col with the reference's raw-reshape row mapping
//   row r = b*1024 + rr ; element c ; g = rr*2304 + c
//   f = g/1024 (feature), l = g%1024 (location)
//   f -> (cc, di, dj), l -> (ho, wo); value = x[b, cc, ho+di-1, wo+dj-1] or 0
// ---------------------------------------------------------------------------
__global__ void im2col_kernel(const float* __restrict__ x) {
    int r = blockIdx.y;                          // 0..8191
    int c = blockIdx.x * 256 + threadIdx.x;      // 0..2303 (9*256 == 2304)
    int b  = r >> 10;
    int rr = r & 1023;
    int g  = rr * KDIM + c;
    int f  = g >> 10;
    int l  = g & 1023;
    int cc = f / 9;
    int t  = f - cc * 9;
    int di = t / 3;
    int dj = t - di * 3;
    int ho = l >> 5;
    int wo = l & 31;
    int hi = ho + di - 1;
    int wi = wo + dj - 1;
    float v = 0.0f;
    if ((unsigned)hi < 32u && (unsigned)wi < 32u)
        v = x[((b * IN_CH + cc) << 10) + (hi << 5) + wi];
    g_X[(size_t)r * KDIM + c] = v;
}

// ---------------------------------------------------------------------------
// Kernel 2: fp32 tiled GEMM  C[M=8192, N=512] = X[M,K=2304] * W_T[K,N]
//   BM=128, BN=128, BK=16, 256 threads, 8x8 micro-tile per thread.
//   Thread->row mapping interleaved so epilogue writes coalesce along rr.
//   Output written directly into NCHW layout: out[b, o, rr].
// ---------------------------------------------------------------------------
#define BM 128
#define BN 128
#define BK 16
#define ASTRIDE (BM + 4)   // pad to break transpose-store bank conflicts

__global__ __launch_bounds__(256, 2) void gemm_kernel(float* __restrict__ out) {
    __shared__ float As[BK][ASTRIDE];
    __shared__ float Bs[BK][BN];

    const int tid = threadIdx.x;
    const int tx  = tid & 15;     // m direction (interleaved, stride 16)
    const int ty  = tid >> 4;     // n direction (interleaved, stride 16)
    const int rowTile = blockIdx.y * BM;
    const int colTile = blockIdx.x * BN;

    // A-tile load mapping: 128 rows x 16 k = 512 float4; 2 per thread
    const int a_row = tid >> 2;            // 0..63 (second pass +64)
    const int a_k4  = (tid & 3) << 2;      // 0,4,8,12
    // B-tile load mapping: 16 k x 128 n = 512 float4; 2 per thread
    const int b_k  = tid >> 5;             // 0..7 (second pass +8)
    const int b_n4 = (tid & 31) << 2;

    const float* Aptr = g_X + (size_t)rowTile * KDIM;
    const float* Bptr = g_WT + colTile;

    float acc[8][8];
#pragma unroll
    for (int i = 0; i < 8; i++)
#pragma unroll
        for (int j = 0; j < 8; j++) acc[i][j] = 0.0f;

    for (int k0 = 0; k0 < KDIM; k0 += BK) {
#pragma unroll
        for (int h = 0; h < 2; h++) {
            int row = a_row + h * 64;
            float4 v = *(const float4*)(Aptr + (size_t)row * KDIM + k0 + a_k4);
            As[a_k4 + 0][row] = v.x;
            As[a_k4 + 1][row] = v.y;
            As[a_k4 + 2][row] = v.z;
            As[a_k4 + 3][row] = v.w;
        }
#pragma unroll
        for (int h = 0; h < 2; h++) {
            int kk = b_k + h * 8;
            float4 v = *(const float4*)(Bptr + (size_t)(k0 + kk) * NDIM + b_n4);
            *(float4*)&Bs[kk][b_n4] = v;
        }
        __syncthreads();

#pragma unroll
        for (int k = 0; k < BK; k++) {
            float a[8], bb[8];
#pragma unroll
            for (int i = 0; i < 8; i++) a[i] = As[k][tx + 16 * i];
#pragma unroll
            for (int j = 0; j < 8; j++) bb[j] = Bs[k][ty + 16 * j];
#pragma unroll
            for (int i = 0; i < 8; i++)
#pragma unroll
                for (int j = 0; j < 8; j++)
                    acc[i][j] += a[i] * bb[j];
        }
        __syncthreads();
    }

    // Epilogue: out[b, o, rr] = C[r, o]; adjacent tx -> adjacent rr (coalesced)
#pragma unroll
    for (int i = 0; i < 8; i++) {
        int r  = rowTile + tx + 16 * i;
        int b  = r >> 10;
        int rr = r & 1023;
#pragma unroll
        for (int j = 0; j < 8; j++) {
            int o = colTile + ty + 16 * j;
            out[((b * NDIM + o) << 10) + rr] = acc[i][j];
        }
    }
}

// ---------------------------------------------------------------------------
extern "C" void kernel_launch(void* const* d_in, const int* in_sizes, int n_in,
                              void* d_out, int out_size) {
    const float* x = (const float*)d_in[0];   // (8, 256, 32, 32) fp32
    const float* w = (const float*)d_in[1];   // (8, 36, 64) fp32
    float* out = (float*)d_out;               // (8, 512, 32, 32) fp32

    wprep_kernel<<<KDIM, NDIM>>>(w);
    im2col_kernel<<<dim3(KDIM / 256, MDIM), 256>>>(x);
    gemm_kernel<<<dim3(NDIM / BN, MDIM / BM), 256>>>(out);
}

// round 6
// speedup vs baseline: 2.5301x; 2.5301x over previous
#include <cuda_runtime.h>
#include <cuda_bf16.h>
#include <cstdint>

// ---------------- problem constants ----------------
#define IN_CH  256
#define QB     36
#define BLK    64
#define KDIM   2304            // QB*BLK
#define NDIM   512
#define MDIM   8192
#define KP     (3*KDIM)        // 6912 : [AhiBhi | AloBhi | AhiBlo]

// ---------------- GEMM tiling ----------------
#define BM_   128
#define BN_   256
#define BKC   64               // K chunk (bf16) = 128 bytes = SW128 row
#define NIT   (KP / BKC)       // 108
#define NTHR  512

#define STG_A 16384            // 128*64*2
#define STG_B 32768            // 256*64*2
#define STG   (STG_A + STG_B)  // 49152
#define NSTAGE 3
#define SMEM_TOTAL (NSTAGE * STG)   // 147456

// ---------------- scratch ----------------
__device__ __nv_bfloat16 g_Ahi[(size_t)MDIM * KDIM];   // 37.7 MB
__device__ __nv_bfloat16 g_Alo[(size_t)MDIM * KDIM];   // 37.7 MB
__device__ __nv_bfloat16 g_Bp [(size_t)NDIM * KP];     // 7.1 MB  [N][K'] K-major

// ---------------- PTX helpers ----------------
__device__ __forceinline__ uint32_t smem_u32(const void* p) {
    uint32_t a;
    asm("{ .reg .u64 t; cvta.to.shared.u64 t, %1; cvt.u32.u64 %0, t; }"
        : "=r"(a) : "l"(p));
    return a;
}
__device__ __forceinline__ void cp16(uint32_t s, const void* g) {
    asm volatile("cp.async.cg.shared.global [%0], [%1], 16;" :: "r"(s), "l"(g));
}
#define CP_COMMIT() asm volatile("cp.async.commit_group;" ::: "memory")
#define CP_WAIT1()  asm volatile("cp.async.wait_group 1;" ::: "memory")

__device__ __forceinline__ void ldm4(uint32_t* r, uint32_t addr) {
    asm volatile("ldmatrix.sync.aligned.m8n8.x4.shared.b16 {%0,%1,%2,%3}, [%4];"
                 : "=r"(r[0]), "=r"(r[1]), "=r"(r[2]), "=r"(r[3]) : "r"(addr));
}
__device__ __forceinline__ void mma16816(float* c, const uint32_t* a, const uint32_t* b) {
    asm volatile(
        "mma.sync.aligned.m16n8k16.row.col.f32.bf16.bf16.f32 "
        "{%0,%1,%2,%3}, {%4,%5,%6,%7}, {%8,%9}, {%0,%1,%2,%3};"
        : "+f"(c[0]), "+f"(c[1]), "+f"(c[2]), "+f"(c[3])
        : "r"(a[0]), "r"(a[1]), "r"(a[2]), "r"(a[3]), "r"(b[0]), "r"(b[1]));
}

// ---------------------------------------------------------------------------
// Kernel 0: expanded circulant weight -> B' [512][6912]
//   regions 0,1 : bf16 hi of W ;  region 2 : bf16 lo of W
//   W[o][c] = w[p][q][(n-m) & 63],  o=p*64+n, c=q*64+m
// ---------------------------------------------------------------------------
__global__ void wprep_kernel(const float* __restrict__ w) {
    int o  = blockIdx.y;
    int kp = blockIdx.x * 256 + threadIdx.x;       // 0..6911 (27*256 = 6912)
    int region = kp / KDIM;
    int c = kp - region * KDIM;
    int p = o >> 6, n = o & 63;
    int q = c >> 6, m = c & 63;
    float v = w[(p * QB + q) * BLK + ((n - m) & 63)];
    __nv_bfloat16 hi = __float2bfloat16(v);
    __nv_bfloat16 res = (region == 2)
        ? __float2bfloat16(v - __bfloat162float(hi)) : hi;
    g_Bp[(size_t)o * KP + kp] = res;
}

// ---------------------------------------------------------------------------
// Kernel 1: im2col with the reference's raw-reshape row mapping; hi/lo split
// ---------------------------------------------------------------------------
__global__ void im2col_kernel(const float* __restrict__ x) {
    int r = blockIdx.y;
    int c = blockIdx.x * 256 + threadIdx.x;
    int b  = r >> 10;
    int rr = r & 1023;
    int g  = rr * KDIM + c;
    int f  = g >> 10;
    int l  = g & 1023;
    int cc = f / 9;
    int t  = f - cc * 9;
    int di = t / 3;
    int dj = t - di * 3;
    int ho = l >> 5;
    int wo = l & 31;
    int hi_ = ho + di - 1;
    int wi_ = wo + dj - 1;
    float v = 0.0f;
    if ((unsigned)hi_ < 32u && (unsigned)wi_ < 32u)
        v = x[((b * IN_CH + cc) << 10) + (hi_ << 5) + wi_];
    __nv_bfloat16 hi = __float2bfloat16(v);
    __nv_bfloat16 lo = __float2bfloat16(v - __bfloat162float(hi));
    size_t idx = (size_t)r * KDIM + c;
    g_Ahi[idx] = hi;
    g_Alo[idx] = lo;
}

// ---------------------------------------------------------------------------
// Kernel 2: bf16 mma.sync GEMM  C[8192,512] = A'[8192,6912] * B'[512,6912]^T
// ---------------------------------------------------------------------------
extern __shared__ char dsm[];

__device__ __forceinline__ void load_stage(int it, int s, int tid,
                                           int rowTile, int colTile, uint32_t sb) {
    int region = it / 36;
    int kloc = (it - region * 36) * BKC;
    const __nv_bfloat16* Ab =
        ((region == 1) ? g_Alo : g_Ahi) + (size_t)rowTile * KDIM + kloc;
    const __nv_bfloat16* Bb = g_Bp + (size_t)colTile * KP + it * BKC;
    uint32_t sA = sb + s * STG;
    uint32_t sB = sA + STG_A;
    // A: 128 rows x 8 chunks(16B) = 1024 -> 2 per thread
#pragma unroll
    for (int t = 0; t < 2; t++) {
        int i = tid + t * NTHR;
        int r = i >> 3, c = i & 7;
        cp16(sA + r * 128 + ((c ^ (r & 7)) << 4), Ab + (size_t)r * KDIM + c * 8);
    }
    // B: 256 rows x 8 chunks = 2048 -> 4 per thread
#pragma unroll
    for (int t = 0; t < 4; t++) {
        int i = tid + t * NTHR;
        int r = i >> 3, c = i & 7;
        cp16(sB + r * 128 + ((c ^ (r & 7)) << 4), Bb + (size_t)r * KP + c * 8);
    }
}

__global__ void __launch_bounds__(NTHR, 1) gemm_mma(float* __restrict__ out) {
    const int tid = threadIdx.x;
    const int wid = tid >> 5, lane = tid & 31;
    const int wm = wid >> 2, wn = wid & 3;          // 4x4 warp grid
    const int rowTile = blockIdx.y * BM_;
    const int colTile = blockIdx.x * BN_;
    const uint32_t sb = smem_u32(dsm);

    // ldmatrix lane-constant addressing
    const int quad = lane >> 3, rq = lane & 7;
    const int a_rowq = ((quad & 1) << 3) + rq;      // row within 16-row A block
    const int a_cq   = quad >> 1;                   // 16B chunk parity
    const int a_xor  = a_rowq & 7;
    const int b_rowq = ((quad >> 1) << 3) + rq;     // row within 16-row B block
    const int b_cq   = quad & 1;
    const int b_xor  = b_rowq & 7;
    const uint32_t Aoff = (uint32_t)((wm * 32 + a_rowq) * 128);
    const uint32_t Boff = (uint32_t)(STG_A + (wn * 64 + b_rowq) * 128);

    float acc[2][8][4];
#pragma unroll
    for (int mt = 0; mt < 2; mt++)
#pragma unroll
        for (int j = 0; j < 8; j++)
#pragma unroll
            for (int v = 0; v < 4; v++) acc[mt][j][v] = 0.0f;

    load_stage(0, 0, tid, rowTile, colTile, sb);
    CP_COMMIT();
    load_stage(1, 1, tid, rowTile, colTile, sb);
    CP_COMMIT();

#pragma unroll 1
    for (int it = 0; it < NIT; it++) {
        int s = it - (it / NSTAGE) * NSTAGE;
        CP_WAIT1();
        __syncthreads();

        uint32_t stageBase = sb + s * STG;
        uint32_t Ab = stageBase + Aoff;
        uint32_t Bb = stageBase + Boff;
#pragma unroll
        for (int ks = 0; ks < 4; ks++) {
            uint32_t a[2][4], b[4][4];
#pragma unroll
            for (int mt = 0; mt < 2; mt++)
                ldm4(a[mt], Ab + mt * 2048 + (((ks * 2 + a_cq) ^ a_xor) << 4));
#pragma unroll
            for (int jp = 0; jp < 4; jp++)
                ldm4(b[jp], Bb + jp * 2048 + (((ks * 2 + b_cq) ^ b_xor) << 4));
#pragma unroll
            for (int mt = 0; mt < 2; mt++)
#pragma unroll
                for (int j = 0; j < 8; j++)
                    mma16816(acc[mt][j], a[mt], &b[j >> 1][(j & 1) * 2]);
        }
        __syncthreads();

        if (it + 2 < NIT)
            load_stage(it + 2, (it + 2) % NSTAGE, tid, rowTile, colTile, sb);
        CP_COMMIT();   // empty groups at tail keep wait_group bookkeeping valid
    }

    // epilogue: C[r][o] -> out[b, o, rr]
    const int g = lane >> 2, tig = lane & 3;
    const int bb = rowTile >> 10;
    const int rrbase = (rowTile & 1023) + wm * 32;
#pragma unroll
    for (int mt = 0; mt < 2; mt++) {
#pragma unroll
        for (int j = 0; j < 8; j++) {
            int o = colTile + wn * 64 + j * 8 + tig * 2;
            int r0 = rrbase + mt * 16 + g;
            float* p0 = out + (((size_t)(bb * NDIM + o)) << 10);
            p0[r0]          = acc[mt][j][0];
            p0[1024 + r0]   = acc[mt][j][1];
            p0[r0 + 8]      = acc[mt][j][2];
            p0[1024 + r0 + 8] = acc[mt][j][3];
        }
    }
}

// ---------------------------------------------------------------------------
extern "C" void kernel_launch(void* const* d_in, const int* in_sizes, int n_in,
                              void* d_out, int out_size) {
    const float* x = (const float*)d_in[0];   // (8, 256, 32, 32) fp32
    const float* w = (const float*)d_in[1];   // (8, 36, 64) fp32
    float* out = (float*)d_out;               // (8, 512, 32, 32) fp32

    cudaFuncSetAttribute(gemm_mma, cudaFuncAttributeMaxDynamicSharedMemorySize,
                         SMEM_TOTAL);

    wprep_kernel<<<dim3(KP / 256, NDIM), 256>>>(w);
    im2col_kernel<<<dim3(KDIM / 256, MDIM), 256>>>(x);
    gemm_mma<<<dim3(NDIM / BN_, MDIM / BM_), NTHR, SMEM_TOTAL>>>(out);
}

// round 7
// speedup vs baseline: 3.8722x; 1.5304x over previous
#include <cuda_runtime.h>
#include <cuda_fp16.h>
#include <cstdint>

// ---------------- problem constants ----------------
#define IN_CH  256
#define QB     36
#define BLK    64
#define KDIM   2304            // QB*BLK
#define NDIM   512
#define MDIM   8192

// ---------------- GEMM tiling ----------------
#define BM_   128
#define BN_   256
#define BKC   64               // K chunk (fp16) = 128 bytes
#define NIT   (KDIM / BKC)     // 36
#define NTHR  512

#define STG_A 16384            // 128*64*2
#define STG_B 32768            // 256*64*2
#define STG   (STG_A + 2*STG_B)        // 81920 : A | Bh | Bl
#define NSTAGE 2
#define SMEM_TOTAL (NSTAGE * STG)      // 163840

// ---------------- scratch ----------------
__device__ __half g_Ah[(size_t)MDIM * KDIM];   // 37.7 MB
__device__ __half g_Bh[(size_t)NDIM * KDIM];   // 2.36 MB
__device__ __half g_Bl[(size_t)NDIM * KDIM];   // 2.36 MB

// ---------------- PTX helpers ----------------
__device__ __forceinline__ uint32_t smem_u32(const void* p) {
    uint32_t a;
    asm("{ .reg .u64 t; cvta.to.shared.u64 t, %1; cvt.u32.u64 %0, t; }"
        : "=r"(a) : "l"(p));
    return a;
}
__device__ __forceinline__ void cp16(uint32_t s, const void* g) {
    asm volatile("cp.async.cg.shared.global [%0], [%1], 16;" :: "r"(s), "l"(g));
}
#define CP_COMMIT() asm volatile("cp.async.commit_group;" ::: "memory")
#define CP_WAIT1()  asm volatile("cp.async.wait_group 1;" ::: "memory")

__device__ __forceinline__ void ldm4(uint32_t* r, uint32_t addr) {
    asm volatile("ldmatrix.sync.aligned.m8n8.x4.shared.b16 {%0,%1,%2,%3}, [%4];"
                 : "=r"(r[0]), "=r"(r[1]), "=r"(r[2]), "=r"(r[3]) : "r"(addr));
}
__device__ __forceinline__ void mma16816(float* c, const uint32_t* a, const uint32_t* b) {
    asm volatile(
        "mma.sync.aligned.m16n8k16.row.col.f32.f16.f16.f32 "
        "{%0,%1,%2,%3}, {%4,%5,%6,%7}, {%8,%9}, {%0,%1,%2,%3};"
        : "+f"(c[0]), "+f"(c[1]), "+f"(c[2]), "+f"(c[3])
        : "r"(a[0]), "r"(a[1]), "r"(a[2]), "r"(a[3]), "r"(b[0]), "r"(b[1]));
}

// ---------------------------------------------------------------------------
// Kernel 0: circulant weight expansion -> fp16 hi/lo, [N][K] K-major
//   W[o][c] = w[p][q][(n-m) & 63],  o=p*64+n, c=q*64+m
// ---------------------------------------------------------------------------
__global__ void wprep_kernel(const float* __restrict__ w) {
    int o = blockIdx.y;
    int c = blockIdx.x * 256 + threadIdx.x;      // 9*256 = 2304
    int p = o >> 6, n = o & 63;
    int q = c >> 6, m = c & 63;
    float v = w[(p * QB + q) * BLK + ((n - m) & 63)];
    __half hi = __float2half_rn(v);
    __half lo = __float2half_rn(v - __half2float(hi));
    size_t idx = (size_t)o * KDIM + c;
    g_Bh[idx] = hi;
    g_Bl[idx] = lo;
}

// ---------------------------------------------------------------------------
// Kernel 1: im2col with the reference's raw-reshape row mapping -> fp16
// ---------------------------------------------------------------------------
__global__ void im2col_kernel(const float* __restrict__ x) {
    int r = blockIdx.y;
    int c = blockIdx.x * 256 + threadIdx.x;
    int b  = r >> 10;
    int rr = r & 1023;
    int g  = rr * KDIM + c;
    int f  = g >> 10;
    int l  = g & 1023;
    int cc = f / 9;
    int t  = f - cc * 9;
    int di = t / 3;
    int dj = t - di * 3;
    int ho = l >> 5;
    int wo = l & 31;
    int hi_ = ho + di - 1;
    int wi_ = wo + dj - 1;
    float v = 0.0f;
    if ((unsigned)hi_ < 32u && (unsigned)wi_ < 32u)
        v = x[((b * IN_CH + cc) << 10) + (hi_ << 5) + wi_];
    g_Ah[(size_t)r * KDIM + c] = __float2half_rn(v);
}

// ---------------------------------------------------------------------------
// Kernel 2: fp16 mma.sync GEMM  C[8192,512] = Ah[8192,2304] * (Bh+Bl)[512,2304]^T
//   One A tile per stage feeds two B passes (hi, lo) into the same accumulator.
// ---------------------------------------------------------------------------
extern __shared__ char dsm[];

__device__ __forceinline__ void load_stage(int it, int s, int tid,
                                           int rowTile, int colTile, uint32_t sb) {
    int kloc = it * BKC;
    const __half* Ab = g_Ah + (size_t)rowTile * KDIM + kloc;
    const __half* Bh = g_Bh + (size_t)colTile * KDIM + kloc;
    const __half* Bl = g_Bl + (size_t)colTile * KDIM + kloc;
    uint32_t sA  = sb + s * STG;
    uint32_t sBh = sA + STG_A;
    uint32_t sBl = sBh + STG_B;
    // A: 128 rows x 8 chunks(16B) = 1024 -> 2 per thread
#pragma unroll
    for (int t = 0; t < 2; t++) {
        int i = tid + t * NTHR;
        int r = i >> 3, c = i & 7;
        cp16(sA + r * 128 + ((c ^ (r & 7)) << 4), Ab + (size_t)r * KDIM + c * 8);
    }
    // Bh/Bl: 256 rows x 8 chunks = 2048 each -> 4+4 per thread
#pragma unroll
    for (int t = 0; t < 4; t++) {
        int i = tid + t * NTHR;
        int r = i >> 3, c = i & 7;
        uint32_t off = (uint32_t)(r * 128 + ((c ^ (r & 7)) << 4));
        size_t goff = (size_t)r * KDIM + c * 8;
        cp16(sBh + off, Bh + goff);
        cp16(sBl + off, Bl + goff);
    }
}

__global__ void __launch_bounds__(NTHR, 1) gemm_mma(float* __restrict__ out) {
    const int tid = threadIdx.x;
    const int wid = tid >> 5, lane = tid & 31;
    const int wm = wid >> 2, wn = wid & 3;          // 4x4 warp grid
    const int rowTile = blockIdx.y * BM_;
    const int colTile = blockIdx.x * BN_;
    const uint32_t sb = smem_u32(dsm);

    // ldmatrix lane-constant addressing
    const int quad = lane >> 3, rq = lane & 7;
    const int a_rowq = ((quad & 1) << 3) + rq;
    const int a_cq   = quad >> 1;
    const int a_xor  = a_rowq & 7;
    const int b_rowq = ((quad >> 1) << 3) + rq;
    const int b_cq   = quad & 1;
    const int b_xor  = b_rowq & 7;
    const uint32_t Aoff  = (uint32_t)((wm * 32 + a_rowq) * 128);
    const uint32_t Bhoff = (uint32_t)(STG_A + (wn * 64 + b_rowq) * 128);
    const uint32_t Bloff = (uint32_t)(STG_A + STG_B + (wn * 64 + b_rowq) * 128);

    float acc[2][8][4];
#pragma unroll
    for (int mt = 0; mt < 2; mt++)
#pragma unroll
        for (int j = 0; j < 8; j++)
#pragma unroll
            for (int v = 0; v < 4; v++) acc[mt][j][v] = 0.0f;

    load_stage(0, 0, tid, rowTile, colTile, sb);
    CP_COMMIT();
    load_stage(1, 1, tid, rowTile, colTile, sb);
    CP_COMMIT();

#pragma unroll 1
    for (int it = 0; it < NIT; it++) {
        int s = it & 1;
        CP_WAIT1();            // group `it` complete (this thread)
        __syncthreads();       // all threads' stage data resident

        uint32_t stageBase = sb + s * STG;
        uint32_t Ab  = stageBase + Aoff;
        uint32_t Bhb = stageBase + Bhoff;
        uint32_t Blb = stageBase + Bloff;
#pragma unroll
        for (int ks = 0; ks < 4; ks++) {
            uint32_t a[2][4], b[4][4];
#pragma unroll
            for (int mt = 0; mt < 2; mt++)
                ldm4(a[mt], Ab + mt * 2048 + (((ks * 2 + a_cq) ^ a_xor) << 4));
            // pass 1: B hi
#pragma unroll
            for (int jp = 0; jp < 4; jp++)
                ldm4(b[jp], Bhb + jp * 2048 + (((ks * 2 + b_cq) ^ b_xor) << 4));
#pragma unroll
            for (int mt = 0; mt < 2; mt++)
#pragma unroll
                for (int j = 0; j < 8; j++)
                    mma16816(acc[mt][j], a[mt], &b[j >> 1][(j & 1) * 2]);
            // pass 2: B lo (same A regs, same accumulators)
#pragma unroll
            for (int jp = 0; jp < 4; jp++)
                ldm4(b[jp], Blb + jp * 2048 + (((ks * 2 + b_cq) ^ b_xor) << 4));
#pragma unroll
            for (int mt = 0; mt < 2; mt++)
#pragma unroll
                for (int j = 0; j < 8; j++)
                    mma16816(acc[mt][j], a[mt], &b[j >> 1][(j & 1) * 2]);
        }
        __syncthreads();       // all reads of stage s done before refill

        if (it + 2 < NIT)
            load_stage(it + 2, s, tid, rowTile, colTile, sb);
        CP_COMMIT();           // empty groups at tail keep bookkeeping valid
    }

    // epilogue: C[r][o] -> out[b, o, rr]
    const int g = lane >> 2, tig = lane & 3;
    const int bb = rowTile >> 10;
    const int rrbase = (rowTile & 1023) + wm * 32;
#pragma unroll
    for (int mt = 0; mt < 2; mt++) {
#pragma unroll
        for (int j = 0; j < 8; j++) {
            int o = colTile + wn * 64 + j * 8 + tig * 2;
            int r0 = rrbase + mt * 16 + g;
            float* p0 = out + (((size_t)(bb * NDIM + o)) << 10);
            p0[r0]            = acc[mt][j][0];
            p0[1024 + r0]     = acc[mt][j][1];
            p0[r0 + 8]        = acc[mt][j][2];
            p0[1024 + r0 + 8] = acc[mt][j][3];
        }
    }
}

// ---------------------------------------------------------------------------
extern "C" void kernel_launch(void* const* d_in, const int* in_sizes, int n_in,
                              void* d_out, int out_size) {
    const float* x = (const float*)d_in[0];   // (8, 256, 32, 32) fp32
    const float* w = (const float*)d_in[1];   // (8, 36, 64) fp32
    float* out = (float*)d_out;               // (8, 512, 32, 32) fp32

    cudaFuncSetAttribute(gemm_mma, cudaFuncAttributeMaxDynamicSharedMemorySize,
                         SMEM_TOTAL);

    wprep_kernel<<<dim3(KDIM / 256, NDIM), 256>>>(w);
    im2col_kernel<<<dim3(KDIM / 256, MDIM), 256>>>(x);
    gemm_mma<<<dim3(NDIM / BN_, MDIM / BM_), NTHR, SMEM_TOTAL>>>(out);
}

// round 9
// speedup vs baseline: 6.2790x; 1.6216x over previous
#include <cuda_runtime.h>
#include <cuda_fp16.h>
#include <cstdint>

// ---------------- problem constants ----------------
#define IN_CH  256
#define QB     36
#define BLK    64
#define KDIM   2304            // QB*BLK
#define NDIM   512
#define MDIM   8192

// ---------------- GEMM tiling ----------------
#define BM_   128
#define BN_   256
#define BKC   64               // K chunk (fp16) = 128 bytes
#define NIT   (KDIM / BKC)     // 36
#define NTHR  512

#define STG_A 16384            // 128*64*2
#define STG_B 32768            // 256*64*2
#define STG   (STG_A + STG_B)  // 49152
#define NSTAGE 3
#define SMEM_TOTAL (NSTAGE * STG)      // 147456

// ---------------- scratch ----------------
__device__ __half g_Ah[(size_t)MDIM * KDIM];   // 37.7 MB
__device__ __half g_B [(size_t)NDIM * KDIM];   // 2.36 MB  [N][K] K-major

// ---------------- PTX helpers ----------------
__device__ __forceinline__ uint32_t smem_u32(const void* p) {
    uint32_t a;
    asm("{ .reg .u64 t; cvta.to.shared.u64 t, %1; cvt.u32.u64 %0, t; }"
        : "=r"(a) : "l"(p));
    return a;
}
__device__ __forceinline__ void cp16(uint32_t s, const void* g) {
    asm volatile("cp.async.cg.shared.global [%0], [%1], 16;" :: "r"(s), "l"(g));
}
#define CP_COMMIT() asm volatile("cp.async.commit_group;" ::: "memory")
#define CP_WAIT1()  asm volatile("cp.async.wait_group 1;" ::: "memory")

__device__ __forceinline__ void ldm4(uint32_t* r, uint32_t addr) {
    asm volatile("ldmatrix.sync.aligned.m8n8.x4.shared.b16 {%0,%1,%2,%3}, [%4];"
                 : "=r"(r[0]), "=r"(r[1]), "=r"(r[2]), "=r"(r[3]) : "r"(addr));
}
__device__ __forceinline__ void mma16816(float* c, const uint32_t* a, const uint32_t* b) {
    asm volatile(
        "mma.sync.aligned.m16n8k16.row.col.f32.f16.f16.f32 "
        "{%0,%1,%2,%3}, {%4,%5,%6,%7}, {%8,%9}, {%0,%1,%2,%3};"
        : "+f"(c[0]), "+f"(c[1]), "+f"(c[2]), "+f"(c[3])
        : "r"(a[0]), "r"(a[1]), "r"(a[2]), "r"(a[3]), "r"(b[0]), "r"(b[1]));
}

// ---------------------------------------------------------------------------
// Kernel 0: circulant weight expansion -> fp16, [N][K] K-major
//   W[o][c] = w[p][q][(n-m) & 63],  o=p*64+n, c=q*64+m
// ---------------------------------------------------------------------------
__global__ void wprep_kernel(const float* __restrict__ w) {
    int o = blockIdx.y;
    int c = blockIdx.x * 256 + threadIdx.x;      // 9*256 = 2304
    int p = o >> 6, n = o & 63;
    int q = c >> 6, m = c & 63;
    float v = w[(p * QB + q) * BLK + ((n - m) & 63)];
    g_B[(size_t)o * KDIM + c] = __float2half_rn(v);
}

// ---------------------------------------------------------------------------
// Kernel 1: im2col, raw-reshape mapping, 4 elems/thread, one 8B store
// ---------------------------------------------------------------------------
__global__ void im2col_kernel(const float* __restrict__ x) {
    int r  = blockIdx.y;
    int c0 = (blockIdx.x * 192 + threadIdx.x) * 4;   // 3*192*4 = 2304
    int b  = r >> 10;
    int rr = r & 1023;
    float v[4];
#pragma unroll
    for (int j = 0; j < 4; j++) {
        int g  = rr * KDIM + c0 + j;
        int f  = g >> 10;
        int l  = g & 1023;
        int cc = f / 9;
        int t  = f - cc * 9;
        int di = t / 3;
        int dj = t - di * 3;
        int ho = l >> 5;
        int wo = l & 31;
        int hi_ = ho + di - 1;
        int wi_ = wo + dj - 1;
        v[j] = 0.0f;
        if ((unsigned)hi_ < 32u && (unsigned)wi_ < 32u)
            v[j] = x[((b * IN_CH + cc) << 10) + (hi_ << 5) + wi_];
    }
    __half2 h01 = __floats2half2_rn(v[0], v[1]);
    __half2 h23 = __floats2half2_rn(v[2], v[3]);
    uint2 st;
    st.x = *(uint32_t*)&h01;
    st.y = *(uint32_t*)&h23;
    *(uint2*)(g_Ah + (size_t)r * KDIM + c0) = st;
}

// ---------------------------------------------------------------------------
// Kernel 2: fp16 mma.sync GEMM  C[8192,512] = Ah[8192,2304] * B[512,2304]^T
//   3-stage cp.async pipeline, one __syncthreads per iteration.
// ---------------------------------------------------------------------------
extern __shared__ char dsm[];

__device__ __forceinline__ void load_stage(int it, int s, int tid,
                                           int rowTile, int colTile, uint32_t sb) {
    int kloc = it * BKC;
    const __half* Ab = g_Ah + (size_t)rowTile * KDIM + kloc;
    const __half* Bb = g_B  + (size_t)colTile * KDIM + kloc;
    uint32_t sA = sb + s * STG;
    uint32_t sB = sA + STG_A;
    // A: 128 rows x 8 chunks(16B) = 1024 -> 2 per thread
#pragma unroll
    for (int t = 0; t < 2; t++) {
        int i = tid + t * NTHR;
        int r = i >> 3, c = i & 7;
        cp16(sA + r * 128 + ((c ^ (r & 7)) << 4), Ab + (size_t)r * KDIM + c * 8);
    }
    // B: 256 rows x 8 chunks = 2048 -> 4 per thread
#pragma unroll
    for (int t = 0; t < 4; t++) {
        int i = tid + t * NTHR;
        int r = i >> 3, c = i & 7;
        cp16(sB + r * 128 + ((c ^ (r & 7)) << 4), Bb + (size_t)r * KDIM + c * 8);
    }
}

__global__ void __launch_bounds__(NTHR, 1) gemm_mma(float* __restrict__ out) {
    const int tid = threadIdx.x;
    const int wid = tid >> 5, lane = tid & 31;
    const int wm = wid >> 2, wn = wid & 3;          // 4x4 warp grid
    const int rowTile = blockIdx.y * BM_;
    const int colTile = blockIdx.x * BN_;
    const uint32_t sb = smem_u32(dsm);

    // ldmatrix lane-constant addressing
    const int quad = lane >> 3, rq = lane & 7;
    const int a_rowq = ((quad & 1) << 3) + rq;
    const int a_cq   = quad >> 1;
    const int a_xor  = a_rowq & 7;
    const int b_rowq = ((quad >> 1) << 3) + rq;
    const int b_cq   = quad & 1;
    const int b_xor  = b_rowq & 7;
    const uint32_t Aoff = (uint32_t)((wm * 32 + a_rowq) * 128);
    const uint32_t Boff = (uint32_t)(STG_A + (wn * 64 + b_rowq) * 128);

    float acc[2][8][4];
#pragma unroll
    for (int mt = 0; mt < 2; mt++)
#pragma unroll
        for (int j = 0; j < 8; j++)
#pragma unroll
            for (int v = 0; v < 4; v++) acc[mt][j][v] = 0.0f;

    load_stage(0, 0, tid, rowTile, colTile, sb);
    CP_COMMIT();
    load_stage(1, 1, tid, rowTile, colTile, sb);
    CP_COMMIT();

#pragma unroll 1
    for (int it = 0; it < NIT; it++) {
        int s = it - (it / NSTAGE) * NSTAGE;
        CP_WAIT1();            // group for chunk `it` complete (this thread)
        __syncthreads();       // all warps finished iter it-1 (stage (it+2)%3 free)

        if (it + 2 < NIT)
            load_stage(it + 2, (it + 2) % NSTAGE, tid, rowTile, colTile, sb);
        CP_COMMIT();           // empty groups at tail keep bookkeeping valid

        uint32_t stageBase = sb + s * STG;
        uint32_t Ab = stageBase + Aoff;
        uint32_t Bb = stageBase + Boff;
#pragma unroll
        for (int ks = 0; ks < 4; ks++) {
            uint32_t a[2][4], b[4][4];
#pragma unroll
            for (int mt = 0; mt < 2; mt++)
                ldm4(a[mt], Ab + mt * 2048 + (((ks * 2 + a_cq) ^ a_xor) << 4));
#pragma unroll
            for (int jp = 0; jp < 4; jp++)
                ldm4(b[jp], Bb + jp * 2048 + (((ks * 2 + b_cq) ^ b_xor) << 4));
#pragma unroll
            for (int mt = 0; mt < 2; mt++)
#pragma unroll
                for (int j = 0; j < 8; j++)
                    mma16816(acc[mt][j], a[mt], &b[j >> 1][(j & 1) * 2]);
        }
    }

    // epilogue: C[r][o] -> out[b, o, rr]
    const int g = lane >> 2, tig = lane & 3;
    const int bb = rowTile >> 10;
    const int rrbase = (rowTile & 1023) + wm * 32;
#pragma unroll
    for (int mt = 0; mt < 2; mt++) {
#pragma unroll
        for (int j = 0; j < 8; j++) {
            int o = colTile + wn * 64 + j * 8 + tig * 2;
            int r0 = rrbase + mt * 16 + g;
            float* p0 = out + (((size_t)(bb * NDIM + o)) << 10);
            p0[r0]            = acc[mt][j][0];
            p0[1024 + r0]     = acc[mt][j][1];
            p0[r0 + 8]        = acc[mt][j][2];
            p0[1024 + r0 + 8] = acc[mt][j][3];
        }
    }
}

// ---------------------------------------------------------------------------
extern "C" void kernel_launch(void* const* d_in, const int* in_sizes, int n_in,
                              void* d_out, int out_size) {
    const float* x = (const float*)d_in[0];   // (8, 256, 32, 32) fp32
    const float* w = (const float*)d_in[1];   // (8, 36, 64) fp32
    float* out = (float*)d_out;               // (8, 512, 32, 32) fp32

    cudaFuncSetAttribute(gemm_mma, cudaFuncAttributeMaxDynamicSharedMemorySize,
                         SMEM_TOTAL);

    wprep_kernel<<<dim3(KDIM / 256, NDIM), 256>>>(w);
    im2col_kernel<<<dim3(3, MDIM), 192>>>(x);
    gemm_mma<<<dim3(NDIM / BN_, MDIM / BM_), NTHR, SMEM_TOTAL>>>(out);
}

// round 12
// speedup vs baseline: 6.7051x; 1.0679x over previous
#include <cuda_runtime.h>
#include <cuda_fp16.h>
#include <cstdint>

// ---------------- problem constants ----------------
#define IN_CH  256
#define QB     36
#define BLK    64
#define KDIM   2304            // QB*BLK
#define NDIM   512
#define MDIM   8192

// ---------------- GEMM tiling ----------------
#define BM_   128
#define BN_   256
#define BKC   64               // K chunk (fp16) = 128 bytes
#define NIT   (KDIM / BKC)     // 36
#define NTHR  512

#define STG_A 16384            // 128*64*2
#define STG_B 32768            // 256*64*2
#define STG   (STG_A + STG_B)  // 49152
#define NSTAGE 4
#define SMEM_TOTAL (NSTAGE * STG)      // 196608

// ---------------- scratch ----------------
__device__ __half g_Ah[(size_t)MDIM * KDIM];   // 37.7 MB
__device__ __half g_B [(size_t)NDIM * KDIM];   // 2.36 MB  [N][K] K-major

// ---------------- PTX helpers ----------------
__device__ __forceinline__ uint32_t smem_u32(const void* p) {
    uint32_t a;
    asm("{ .reg .u64 t; cvta.to.shared.u64 t, %1; cvt.u32.u64 %0, t; }"
        : "=r"(a) : "l"(p));
    return a;
}
__device__ __forceinline__ void cp16(uint32_t s, const void* g) {
    asm volatile("cp.async.cg.shared.global [%0], [%1], 16;" :: "r"(s), "l"(g));
}
#define CP_COMMIT() asm volatile("cp.async.commit_group;" ::: "memory")
#define CP_WAIT2()  asm volatile("cp.async.wait_group 2;" ::: "memory")

__device__ __forceinline__ void ldm4(uint32_t* r, uint32_t addr) {
    asm volatile("ldmatrix.sync.aligned.m8n8.x4.shared.b16 {%0,%1,%2,%3}, [%4];"
                 : "=r"(r[0]), "=r"(r[1]), "=r"(r[2]), "=r"(r[3]) : "r"(addr));
}
__device__ __forceinline__ void mma16816(float* c, const uint32_t* a, const uint32_t* b) {
    asm volatile(
        "mma.sync.aligned.m16n8k16.row.col.f32.f16.f16.f32 "
        "{%0,%1,%2,%3}, {%4,%5,%6,%7}, {%8,%9}, {%0,%1,%2,%3};"
        : "+f"(c[0]), "+f"(c[1]), "+f"(c[2]), "+f"(c[3])
        : "r"(a[0]), "r"(a[1]), "r"(a[2]), "r"(a[3]), "r"(b[0]), "r"(b[1]));
}

// ---------------------------------------------------------------------------
// Kernel 0: fused prep.  Blocks [0, 24576): im2col (4 elems/thread, 8B store).
//                        Blocks [24576, 26112): circulant weight expansion.
// ---------------------------------------------------------------------------
#define IM2COL_BLOCKS (3 * MDIM)                 // 24576, 192 thr, 4 elems
#define WPREP_BLOCKS  ((NDIM * KDIM) / (192*4))  // 1536
__global__ void prep_kernel(const float* __restrict__ x,
                            const float* __restrict__ w) {
    int bid = blockIdx.x;
    if (bid < IM2COL_BLOCKS) {
        int r  = bid / 3;
        int c0 = ((bid - r * 3) * 192 + threadIdx.x) * 4;  // 3*192*4 = 2304
        int b  = r >> 10;
        int rr = r & 1023;
        float v[4];
#pragma unroll
        for (int j = 0; j < 4; j++) {
            int g  = rr * KDIM + c0 + j;
            int f  = g >> 10;
            int l  = g & 1023;
            int cc = f / 9;
            int t  = f - cc * 9;
            int di = t / 3;
            int dj = t - di * 3;
            int ho = l >> 5;
            int wo = l & 31;
            int hi_ = ho + di - 1;
            int wi_ = wo + dj - 1;
            v[j] = 0.0f;
            if ((unsigned)hi_ < 32u && (unsigned)wi_ < 32u)
                v[j] = x[((b * IN_CH + cc) << 10) + (hi_ << 5) + wi_];
        }
        __half2 h01 = __floats2half2_rn(v[0], v[1]);
        __half2 h23 = __floats2half2_rn(v[2], v[3]);
        uint2 st;
        st.x = *(uint32_t*)&h01;
        st.y = *(uint32_t*)&h23;
        *(uint2*)(g_Ah + (size_t)r * KDIM + c0) = st;
    } else {
        // W[o][c] = w[p][q][(n-m)&63], o=p*64+n, c=q*64+m ; 4 c per thread
        int idx0 = ((bid - IM2COL_BLOCKS) * 192 + threadIdx.x) * 4;
        int o = idx0 / KDIM;
        int c = idx0 - o * KDIM;                 // KDIM%4==0 -> same row
        int p = o >> 6, n = o & 63;
        int q = c >> 6;                          // 4 consecutive c share q
        float v[4];
#pragma unroll
        for (int j = 0; j < 4; j++) {
            int m = (c + j) & 63;
            v[j] = w[(p * QB + q) * BLK + ((n - m) & 63)];
        }
        __half2 h01 = __floats2half2_rn(v[0], v[1]);
        __half2 h23 = __floats2half2_rn(v[2], v[3]);
        uint2 st;
        st.x = *(uint32_t*)&h01;
        st.y = *(uint32_t*)&h23;
        *(uint2*)(g_B + (size_t)o * KDIM + c) = st;
    }
}

// ---------------------------------------------------------------------------
// Kernel 1: fp16 mma.sync GEMM  C[8192,512] = Ah[8192,2304] * B[512,2304]^T
//   4-stage cp.async pipeline, prefetch distance 3, one barrier per iter.
// ---------------------------------------------------------------------------
extern __shared__ char dsm[];

__device__ __forceinline__ void load_stage(int it, int s, int tid,
                                           int rowTile, int colTile, uint32_t sb) {
    int kloc = it * BKC;
    const __half* Ab = g_Ah + (size_t)rowTile * KDIM + kloc;
    const __half* Bb = g_B  + (size_t)colTile * KDIM + kloc;
    uint32_t sA = sb + s * STG;
    uint32_t sB = sA + STG_A;
    // A: 128 rows x 8 chunks(16B) = 1024 -> 2 per thread
#pragma unroll
    for (int t = 0; t < 2; t++) {
        int i = tid + t * NTHR;
        int r = i >> 3, c = i & 7;
        cp16(sA + r * 128 + ((c ^ (r & 7)) << 4), Ab + (size_t)r * KDIM + c * 8);
    }
    // B: 256 rows x 8 chunks = 2048 -> 4 per thread
#pragma unroll
    for (int t = 0; t < 4; t++) {
        int i = tid + t * NTHR;
        int r = i >> 3, c = i & 7;
        cp16(sB + r * 128 + ((c ^ (r & 7)) << 4), Bb + (size_t)r * KDIM + c * 8);
    }
}

__global__ void __launch_bounds__(NTHR, 1) gemm_mma(float* __restrict__ out) {
    const int tid = threadIdx.x;
    const int wid = tid >> 5, lane = tid & 31;
    const int wm = wid >> 2, wn = wid & 3;          // 4x4 warp grid
    const int rowTile = blockIdx.y * BM_;
    const int colTile = blockIdx.x * BN_;
    const uint32_t sb = smem_u32(dsm);

    // ldmatrix lane-constant addressing
    const int quad = lane >> 3, rq = lane & 7;
    const int a_rowq = ((quad & 1) << 3) + rq;
    const int a_cq   = quad >> 1;
    const int a_xor  = a_rowq & 7;
    const int b_rowq = ((quad >> 1) << 3) + rq;
    const int b_cq   = quad & 1;
    const int b_xor  = b_rowq & 7;
    const uint32_t Aoff = (uint32_t)((wm * 32 + a_rowq) * 128);
    const uint32_t Boff = (uint32_t)(STG_A + (wn * 64 + b_rowq) * 128);

    float acc[2][8][4];
#pragma unroll
    for (int mt = 0; mt < 2; mt++)
#pragma unroll
        for (int j = 0; j < 8; j++)
#pragma unroll
            for (int v = 0; v < 4; v++) acc[mt][j][v] = 0.0f;

    load_stage(0, 0, tid, rowTile, colTile, sb);
    CP_COMMIT();
    load_stage(1, 1, tid, rowTile, colTile, sb);
    CP_COMMIT();
    load_stage(2, 2, tid, rowTile, colTile, sb);
    CP_COMMIT();

#pragma unroll 1
    for (int it = 0; it < NIT; it++) {
        int s = it & 3;
        CP_WAIT2();            // <=2 groups outstanding -> chunk `it` resident
        __syncthreads();       // all warps done with iter it-1 (stage (it+3)%4 free)

        if (it + 3 < NIT)
            load_stage(it + 3, (it + 3) & 3, tid, rowTile, colTile, sb);
        CP_COMMIT();           // empty groups at tail keep bookkeeping valid

        uint32_t stageBase = sb + s * STG;
        uint32_t Ab = stageBase + Aoff;
        uint32_t Bb = stageBase + Boff;
#pragma unroll
        for (int ks = 0; ks < 4; ks++) {
            uint32_t a[2][4], b[4][4];
#pragma unroll
            for (int mt = 0; mt < 2; mt++)
                ldm4(a[mt], Ab + mt * 2048 + (((ks * 2 + a_cq) ^ a_xor) << 4));
#pragma unroll
            for (int jp = 0; jp < 4; jp++)
                ldm4(b[jp], Bb + jp * 2048 + (((ks * 2 + b_cq) ^ b_xor) << 4));
#pragma unroll
            for (int mt = 0; mt < 2; mt++)
#pragma unroll
                for (int j = 0; j < 8; j++)
                    mma16816(acc[mt][j], a[mt], &b[j >> 1][(j & 1) * 2]);
        }
    }

    // epilogue: C[r][o] -> out[b, o, rr]
    const int g = lane >> 2, tig = lane & 3;
    const int bb = rowTile >> 10;
    const int rrbase = (rowTile & 1023) + wm * 32;
#pragma unroll
    for (int mt = 0; mt < 2; mt++) {
#pragma unroll
        for (int j = 0; j < 8; j++) {
            int o = colTile + wn * 64 + j * 8 + tig * 2;
            int r0 = rrbase + mt * 16 + g;
            float* p0 = out + (((size_t)(bb * NDIM + o)) << 10);
            p0[r0]            = acc[mt][j][0];
            p0[1024 + r0]     = acc[mt][j][1];
            p0[r0 + 8]        = acc[mt][j][2];
            p0[1024 + r0 + 8] = acc[mt][j][3];
        }
    }
}

// ---------------------------------------------------------------------------
extern "C" void kernel_launch(void* const* d_in, const int* in_sizes, int n_in,
                              void* d_out, int out_size) {
    const float* x = (const float*)d_in[0];   // (8, 256, 32, 32) fp32
    const float* w = (const float*)d_in[1];   // (8, 36, 64) fp32
    float* out = (float*)d_out;               // (8, 512, 32, 32) fp32

    cudaFuncSetAttribute(gemm_mma, cudaFuncAttributeMaxDynamicSharedMemorySize,
                         SMEM_TOTAL);

    prep_kernel<<<IM2COL_BLOCKS + WPREP_BLOCKS, 192>>>(x, w);
    gemm_mma<<<dim3(NDIM / BN_, MDIM / BM_), NTHR, SMEM_TOTAL>>>(out);
}